// round 8
// baseline (speedup 1.0000x reference)
#include <cuda_runtime.h>
#include <cstdint>

// Problem constants (fixed-shape problem)
#define NNODES 100000
#define NEDGES 3200000
#define FIN    500
#define HID    64
#define NC     64
#define KF     5
#define DH     10
#define NF     (NNODES * 64)
#define NB     ((NNODES + 255) / 256)   // 391 scan blocks

// ---------------- device scratch (no allocation allowed) ----------------
__device__ float g_X[NF];        // MLP output (Tx_0)
__device__ float g_A[NF];        // ping
__device__ float g_B[NF];        // pong
__device__ float g_H[NF];        // hidden accumulator (seeded in hop 1)
__device__ int2  g_csr[NEDGES];  // {src_node, weight_bits}, grouped by dst
__device__ int   g_rowptr[NNODES];
__device__ int   g_rowend[NNODES];  // fill cursor; after fill == row end
__device__ int   g_cnt[NNODES];     // in-degree histogram (by dst)
__device__ int   g_deg[NNODES];     // out-degree (by src, non-loop)
__device__ float g_dinv[NNODES];
__device__ int   g_bsum[NB + 1];
__device__ float g_coeff[16];
__device__ int   g_is64;

// ---------------- edge access (int32 or int64, runtime-detected) --------
__device__ __forceinline__ void load_edge(const void* edges, int e, int& s, int& d) {
    if (g_is64) {
        s = (int)((const long long*)edges)[e];
        d = (int)((const long long*)edges)[NEDGES + e];
    } else {
        s = ((const int*)edges)[e];
        d = ((const int*)edges)[NEDGES + e];
    }
}

// ---------------- init: zero counters, assume int64 until disproven -----
__global__ void k_init0() {
    int i = blockIdx.x * blockDim.x + threadIdx.x;
    if (i < NNODES) { g_deg[i] = 0; g_cnt[i] = 0; }
    if (i == 0) g_is64 = 1;
}

// If data is int64, high words of values < 2^31 are all zero; if int32,
// odd words are random node IDs (prob of 4096 zeros ~ 0). Samples stay
// within the first row so int32 buffers are never read out of bounds.
__global__ void k_detect(const int* e32) {
    bool nz = false;
    for (int j = threadIdx.x; j < 4096; j += blockDim.x)
        if (e32[2 * j + 1] != 0) nz = true;
    if (nz) g_is64 = 0;   // benign race: all writers store 0
}

// ---------------- degree (by src) and in-degree histogram (by dst) ------
__global__ void k_deg(const void* edges) {
    int e = blockIdx.x * blockDim.x + threadIdx.x;
    if (e >= NEDGES) return;
    int s, d; load_edge(edges, e, s, d);
    if (s != d) {
        atomicAdd(&g_deg[s], 1);
        atomicAdd(&g_cnt[d], 1);
    }
}

__global__ void k_dinv() {
    int i = blockIdx.x * blockDim.x + threadIdx.x;
    if (i >= NNODES) return;
    int d = g_deg[i];
    g_dinv[i] = (d > 0) ? rsqrtf((float)d) : 0.0f;
}

// ---------------- exclusive scan of g_cnt -> g_rowptr (3 kernels) -------
__global__ void k_scan1() {   // per-block Hillis-Steele, 256/block
    __shared__ int sh[256];
    int i = blockIdx.x * 256 + threadIdx.x;
    int v = (i < NNODES) ? g_cnt[i] : 0;
    sh[threadIdx.x] = v;
    __syncthreads();
    int acc = v;
    #pragma unroll
    for (int o = 1; o < 256; o <<= 1) {
        int t = (threadIdx.x >= o) ? sh[threadIdx.x - o] : 0;
        __syncthreads();
        acc += t;
        sh[threadIdx.x] = acc;
        __syncthreads();
    }
    if (i < NNODES) g_rowptr[i] = acc - v;   // exclusive within block
    if (threadIdx.x == 255) g_bsum[blockIdx.x] = acc;
}

__global__ void k_scan2() {   // single block scans NB block sums (exclusive)
    __shared__ int sh[512];
    int v = (threadIdx.x < NB) ? g_bsum[threadIdx.x] : 0;
    sh[threadIdx.x] = v;
    __syncthreads();
    int acc = v;
    #pragma unroll
    for (int o = 1; o < 512; o <<= 1) {
        int t = (threadIdx.x >= o) ? sh[threadIdx.x - o] : 0;
        __syncthreads();
        acc += t;
        sh[threadIdx.x] = acc;
        __syncthreads();
    }
    if (threadIdx.x < NB) g_bsum[threadIdx.x] = acc - v;  // exclusive
}

__global__ void k_scan3() {   // add block offsets; init fill cursor
    int i = blockIdx.x * 256 + threadIdx.x;
    if (i >= NNODES) return;
    int r = g_rowptr[i] + g_bsum[blockIdx.x];
    g_rowptr[i] = r;
    g_rowend[i] = r;          // cursor starts at row base
}

// ---------------- CSR fill: weight folded in ----------------------------
__global__ void k_fill(const void* edges) {
    int e = blockIdx.x * blockDim.x + threadIdx.x;
    if (e >= NEDGES) return;
    int s, d; load_edge(edges, e, s, d);
    if (s == d) return;
    // lam = 2*max(max(w_off),1) = 2 since all w_off <= 0 -> scale=1, diag=0
    float w = -(g_dinv[s] * g_dinv[d]);
    int pos = atomicAdd(&g_rowend[d], 1);
    g_csr[pos] = make_int2(s, __float_as_int(w));
}

// ---------------- Taylor coefficients: coeff = alpha@SINC + beta@COSC ---
__global__ void k_coeff(const float* __restrict__ alpha, const float* __restrict__ beta) {
    int d = threadIdx.x;
    if (d > DH) return;
    double acc = 0.0;
    for (int k = 0; k < KF; k++) {
        double x = (double)(k + 1) * 3.14159265358979323846;  // OMEGA = 1
        double fact = 1.0, xp = 1.0;
        for (int j = 1; j <= d; j++) { fact *= (double)j; xp *= x; }
        float sc = 0.f, cc = 0.f;
        if ((d & 1) == 0) { int m = d / 2;       cc = (float)(((m & 1) ? -1.0 : 1.0) * xp / fact); }
        else              { int m = (d - 1) / 2; sc = (float)(((m & 1) ? -1.0 : 1.0) * xp / fact); }
        acc += (double)alpha[k] * (double)sc + (double)beta[k] * (double)cc;
    }
    g_coeff[d] = (float)acc;
}

// ---------------- fused 2-layer MLP: X = relu(F@W1+b1)@W2+b2 ------------
// Block: 64 nodes x 64 outputs. 256 threads as 16x16, 4x4 per thread.
__global__ __launch_bounds__(256) void k_mlp(
    const float* __restrict__ feat, const float* __restrict__ W1,
    const float* __restrict__ b1,  const float* __restrict__ W2,
    const float* __restrict__ b2)
{
    __shared__ float sF[64][21];    // 64 nodes x BK=20 (+pad)
    __shared__ float sW[20][64];
    __shared__ float sH[64][65];    // hidden (+pad)
    __shared__ float sW2[64][64];
    __shared__ float sB1[64];
    __shared__ float sB2[64];

    const int tx = threadIdx.x & 15;
    const int ty = threadIdx.x >> 4;
    const int n0 = blockIdx.x * 64;

    for (int i = threadIdx.x; i < 64 * 64; i += 256) sW2[i >> 6][i & 63] = W2[i];
    if (threadIdx.x < 64) { sB1[threadIdx.x] = b1[threadIdx.x]; sB2[threadIdx.x] = b2[threadIdx.x]; }

    float acc[4][4];
    #pragma unroll
    for (int i = 0; i < 4; i++)
        #pragma unroll
        for (int j = 0; j < 4; j++) acc[i][j] = 0.f;

    for (int kc = 0; kc < FIN; kc += 20) {
        for (int i = threadIdx.x; i < 64 * 20; i += 256) {
            int r = i / 20, c = i % 20;
            int n = n0 + r;
            sF[r][c] = (n < NNODES) ? feat[(long long)n * FIN + kc + c] : 0.f;
        }
        for (int i = threadIdx.x; i < 20 * 64; i += 256) {
            int r = i >> 6, c = i & 63;
            sW[r][c] = W1[(kc + r) * HID + c];
        }
        __syncthreads();
        #pragma unroll
        for (int k = 0; k < 20; k++) {
            float a[4], b[4];
            #pragma unroll
            for (int j = 0; j < 4; j++) { a[j] = sF[ty * 4 + j][k]; b[j] = sW[k][tx * 4 + j]; }
            #pragma unroll
            for (int i = 0; i < 4; i++)
                #pragma unroll
                for (int j = 0; j < 4; j++) acc[i][j] = fmaf(a[i], b[j], acc[i][j]);
        }
        __syncthreads();
    }

    #pragma unroll
    for (int i = 0; i < 4; i++)
        #pragma unroll
        for (int j = 0; j < 4; j++)
            sH[ty * 4 + i][tx * 4 + j] = fmaxf(acc[i][j] + sB1[tx * 4 + j], 0.f);
    __syncthreads();

    float acc2[4][4];
    #pragma unroll
    for (int i = 0; i < 4; i++)
        #pragma unroll
        for (int j = 0; j < 4; j++) acc2[i][j] = 0.f;
    #pragma unroll 8
    for (int k = 0; k < 64; k++) {
        float a[4], b[4];
        #pragma unroll
        for (int j = 0; j < 4; j++) { a[j] = sH[ty * 4 + j][k]; b[j] = sW2[k][tx * 4 + j]; }
        #pragma unroll
        for (int i = 0; i < 4; i++)
            #pragma unroll
            for (int j = 0; j < 4; j++) acc2[i][j] = fmaf(a[i], b[j], acc2[i][j]);
    }
    #pragma unroll
    for (int i = 0; i < 4; i++) {
        int n = n0 + ty * 4 + i;
        if (n < NNODES) {
            #pragma unroll
            for (int j = 0; j < 4; j++)
                g_X[(long long)n * 64 + tx * 4 + j] = acc2[i][j] + sB2[tx * 4 + j];
        }
    }
}

// ---------------- fused SpMV hop: Tx_d = A*Tx_{d-1}; H += c_d*Tx_d ------
// One warp per dst node, 2 floats (float2) per lane. Pure gather, no
// atomics: each warp exclusively owns its output row and its H row.
// Hop 1 seeds H = (1+c0)*X + c1*Tx_1 (no separate hinit pass).
// Cache policy: CSR meta + H are dead after this kernel -> streaming
// (__ldcs/__stcs). The dst (Tx_d) write is NOT streaming: it is the next
// hop's high-reuse gather operand (~32x/line) and must stay L2-resident.
// On the last hop, fold log_softmax in and write the final output.
__global__ __launch_bounds__(256) void k_spmv(int d, int srcsel, float* __restrict__ out) {
    int n = (blockIdx.x * blockDim.x + threadIdx.x) >> 5;
    int lane = threadIdx.x & 31;
    if (n >= NNODES) return;

    const float2* __restrict__ src =
        (const float2*)(srcsel == 0 ? g_X : (srcsel == 1 ? g_A : g_B));
    float2* dst = (float2*)((d & 1) ? g_B : g_A);

    int e  = __ldg(&g_rowptr[n]);
    int e1 = __ldg(&g_rowend[n]);
    float2 acc = make_float2(0.f, 0.f);

    // 8-deep software pipeline: covers ~250-cyc L2-hit latency (MLP_eff >= 8)
    for (; e + 8 <= e1; e += 8) {
        int2 m[8];
        #pragma unroll
        for (int j = 0; j < 8; j++) m[j] = __ldcs(&g_csr[e + j]);
        float2 v[8];
        #pragma unroll
        for (int j = 0; j < 8; j++) v[j] = src[m[j].x * 32 + lane];
        #pragma unroll
        for (int j = 0; j < 8; j++) {
            float w = __int_as_float(m[j].y);
            acc.x = fmaf(w, v[j].x, acc.x);
            acc.y = fmaf(w, v[j].y, acc.y);
        }
    }
    for (; e < e1; e++) {
        int2 m = __ldcs(&g_csr[e]);
        float w = __int_as_float(m.y);
        float2 v = src[m.x * 32 + lane];
        acc.x = fmaf(w, v.x, acc.x);
        acc.y = fmaf(w, v.y, acc.y);
    }

    float c = g_coeff[d];
    int base = n * 32 + lane;
    float2* H2 = (float2*)g_H;

    float2 h;
    if (d == 1) {
        // seed: H = (1+c0)*X + c1*Tx_1   (src == X on hop 1)
        float s0 = 1.0f + g_coeff[0];
        float2 x0 = ((const float2*)g_X)[base];
        h.x = fmaf(c, acc.x, s0 * x0.x);
        h.y = fmaf(c, acc.y, s0 * x0.y);
    } else {
        h = __ldcs(&H2[base]);
        h.x = fmaf(c, acc.x, h.x);
        h.y = fmaf(c, acc.y, h.y);
    }

    if (d < DH) {
        dst[base] = acc;          // keep resident: next hop's gather operand
        __stcs(&H2[base], h);     // dead until next hop's epilogue
    } else {
        // fused log_softmax over the 64-class row held by this warp
        float m = fmaxf(h.x, h.y);
        #pragma unroll
        for (int o = 16; o; o >>= 1) m = fmaxf(m, __shfl_xor_sync(0xFFFFFFFFu, m, o));
        float sm = expf(h.x - m) + expf(h.y - m);
        #pragma unroll
        for (int o = 16; o; o >>= 1) sm += __shfl_xor_sync(0xFFFFFFFFu, sm, o);
        float l = m + logf(sm);
        __stcs(&((float2*)out)[base], make_float2(h.x - l, h.y - l));
    }
}

// ---------------- launch ------------------------------------------------
extern "C" void kernel_launch(void* const* d_in, const int* in_sizes, int n_in,
                              void* d_out, int out_size) {
    const float* feat  = (const float*)d_in[0];
    const void*  edges = d_in[1];
    const float* W1    = (const float*)d_in[2];
    const float* b1    = (const float*)d_in[3];
    const float* W2    = (const float*)d_in[4];
    const float* b2    = (const float*)d_in[5];
    const float* alpha = (const float*)d_in[6];
    const float* beta  = (const float*)d_in[7];
    float* out = (float*)d_out;

    const int T = 256;
    k_init0<<<(NNODES + T - 1) / T, T>>>();
    k_detect<<<1, 256>>>((const int*)edges);
    k_deg<<<(NEDGES + T - 1) / T, T>>>(edges);
    k_dinv<<<(NNODES + T - 1) / T, T>>>();
    k_scan1<<<NB, 256>>>();
    k_scan2<<<1, 512>>>();
    k_scan3<<<NB, 256>>>();
    k_fill<<<(NEDGES + T - 1) / T, T>>>(edges);
    k_coeff<<<1, 32>>>(alpha, beta);
    k_mlp<<<(NNODES + 63) / 64, 256>>>(feat, W1, b1, W2, b2);

    const int spmv_blocks = (NNODES * 32 + T - 1) / T;
    for (int d = 1; d <= DH; d++) {
        int srcsel = (d == 1) ? 0 : (((d - 1) & 1) ? 2 : 1);  // prev hop's dst
        k_spmv<<<spmv_blocks, T>>>(d, srcsel, out);
    }
}

// round 11
// speedup vs baseline: 1.0980x; 1.0980x over previous
#include <cuda_runtime.h>
#include <cstdint>

// Problem constants (fixed-shape problem)
#define NNODES 100000
#define NEDGES 3200000
#define FIN    500
#define HID    64
#define NC     64
#define KF     5
#define DH     10
#define NF     (NNODES * 64)
#define NB     ((NNODES + 255) / 256)   // 391 scan blocks

// ---------------- device scratch (no allocation allowed) ----------------
__device__ float g_X[NF];        // MLP output (Tx_0)
__device__ float g_A[NF];        // ping
__device__ float g_B[NF];        // pong
__device__ float g_H[NF];        // hidden accumulator (seeded in hop 1)
__device__ int2  g_csr[NEDGES];  // {src_node, weight_bits}, grouped by dst
__device__ int   g_rowptr[NNODES];
__device__ int   g_rowend[NNODES];  // fill cursor; after fill == row end
__device__ int   g_cnt[NNODES];     // in-degree histogram (by dst)
__device__ int   g_deg[NNODES];     // out-degree (by src, non-loop)
__device__ float g_dinv[NNODES];
__device__ int   g_bsum[NB + 1];
__device__ float g_coeff[16];
__device__ int   g_is64;

// ---------------- edge access (int32 or int64, runtime-detected) --------
__device__ __forceinline__ void load_edge(const void* edges, int e, int& s, int& d) {
    if (g_is64) {
        s = (int)((const long long*)edges)[e];
        d = (int)((const long long*)edges)[NEDGES + e];
    } else {
        s = ((const int*)edges)[e];
        d = ((const int*)edges)[NEDGES + e];
    }
}

// ---------------- init: zero counters, assume int64 until disproven -----
__global__ void k_init0() {
    int i = blockIdx.x * blockDim.x + threadIdx.x;
    if (i < NNODES) { g_deg[i] = 0; g_cnt[i] = 0; }
    if (i == 0) g_is64 = 1;
}

// If data is int64, high words of values < 2^31 are all zero; if int32,
// odd words are random node IDs (prob of 4096 zeros ~ 0). Samples stay
// within the first row so int32 buffers are never read out of bounds.
__global__ void k_detect(const int* e32) {
    bool nz = false;
    for (int j = threadIdx.x; j < 4096; j += blockDim.x)
        if (e32[2 * j + 1] != 0) nz = true;
    if (nz) g_is64 = 0;   // benign race: all writers store 0
}

// ---------------- degree (by src) and in-degree histogram (by dst) ------
__global__ void k_deg(const void* edges) {
    int e = blockIdx.x * blockDim.x + threadIdx.x;
    if (e >= NEDGES) return;
    int s, d; load_edge(edges, e, s, d);
    if (s != d) {
        atomicAdd(&g_deg[s], 1);
        atomicAdd(&g_cnt[d], 1);
    }
}

__global__ void k_dinv() {
    int i = blockIdx.x * blockDim.x + threadIdx.x;
    if (i >= NNODES) return;
    int d = g_deg[i];
    g_dinv[i] = (d > 0) ? rsqrtf((float)d) : 0.0f;
}

// ---------------- exclusive scan of g_cnt -> g_rowptr (3 kernels) -------
__global__ void k_scan1() {   // per-block Hillis-Steele, 256/block
    __shared__ int sh[256];
    int i = blockIdx.x * 256 + threadIdx.x;
    int v = (i < NNODES) ? g_cnt[i] : 0;
    sh[threadIdx.x] = v;
    __syncthreads();
    int acc = v;
    #pragma unroll
    for (int o = 1; o < 256; o <<= 1) {
        int t = (threadIdx.x >= o) ? sh[threadIdx.x - o] : 0;
        __syncthreads();
        acc += t;
        sh[threadIdx.x] = acc;
        __syncthreads();
    }
    if (i < NNODES) g_rowptr[i] = acc - v;   // exclusive within block
    if (threadIdx.x == 255) g_bsum[blockIdx.x] = acc;
}

__global__ void k_scan2() {   // single block scans NB block sums (exclusive)
    __shared__ int sh[512];
    int v = (threadIdx.x < NB) ? g_bsum[threadIdx.x] : 0;
    sh[threadIdx.x] = v;
    __syncthreads();
    int acc = v;
    #pragma unroll
    for (int o = 1; o < 512; o <<= 1) {
        int t = (threadIdx.x >= o) ? sh[threadIdx.x - o] : 0;
        __syncthreads();
        acc += t;
        sh[threadIdx.x] = acc;
        __syncthreads();
    }
    if (threadIdx.x < NB) g_bsum[threadIdx.x] = acc - v;  // exclusive
}

__global__ void k_scan3() {   // add block offsets; init fill cursor
    int i = blockIdx.x * 256 + threadIdx.x;
    if (i >= NNODES) return;
    int r = g_rowptr[i] + g_bsum[blockIdx.x];
    g_rowptr[i] = r;
    g_rowend[i] = r;          // cursor starts at row base
}

// ---------------- CSR fill: weight folded in ----------------------------
__global__ void k_fill(const void* edges) {
    int e = blockIdx.x * blockDim.x + threadIdx.x;
    if (e >= NEDGES) return;
    int s, d; load_edge(edges, e, s, d);
    if (s == d) return;
    // lam = 2*max(max(w_off),1) = 2 since all w_off <= 0 -> scale=1, diag=0
    float w = -(g_dinv[s] * g_dinv[d]);
    int pos = atomicAdd(&g_rowend[d], 1);
    g_csr[pos] = make_int2(s, __float_as_int(w));
}

// ---------------- Taylor coefficients: coeff = alpha@SINC + beta@COSC ---
__global__ void k_coeff(const float* __restrict__ alpha, const float* __restrict__ beta) {
    int d = threadIdx.x;
    if (d > DH) return;
    double acc = 0.0;
    for (int k = 0; k < KF; k++) {
        double x = (double)(k + 1) * 3.14159265358979323846;  // OMEGA = 1
        double fact = 1.0, xp = 1.0;
        for (int j = 1; j <= d; j++) { fact *= (double)j; xp *= x; }
        float sc = 0.f, cc = 0.f;
        if ((d & 1) == 0) { int m = d / 2;       cc = (float)(((m & 1) ? -1.0 : 1.0) * xp / fact); }
        else              { int m = (d - 1) / 2; sc = (float)(((m & 1) ? -1.0 : 1.0) * xp / fact); }
        acc += (double)alpha[k] * (double)sc + (double)beta[k] * (double)cc;
    }
    g_coeff[d] = (float)acc;
}

// ---------------- fused 2-layer MLP: X = relu(F@W1+b1)@W2+b2 ------------
// Block: 64 nodes x 64 outputs. 256 threads as 16x16, 4x4 per thread.
__global__ __launch_bounds__(256) void k_mlp(
    const float* __restrict__ feat, const float* __restrict__ W1,
    const float* __restrict__ b1,  const float* __restrict__ W2,
    const float* __restrict__ b2)
{
    __shared__ float sF[64][21];    // 64 nodes x BK=20 (+pad)
    __shared__ float sW[20][64];
    __shared__ float sH[64][65];    // hidden (+pad)
    __shared__ float sW2[64][64];
    __shared__ float sB1[64];
    __shared__ float sB2[64];

    const int tx = threadIdx.x & 15;
    const int ty = threadIdx.x >> 4;
    const int n0 = blockIdx.x * 64;

    for (int i = threadIdx.x; i < 64 * 64; i += 256) sW2[i >> 6][i & 63] = W2[i];
    if (threadIdx.x < 64) { sB1[threadIdx.x] = b1[threadIdx.x]; sB2[threadIdx.x] = b2[threadIdx.x]; }

    float acc[4][4];
    #pragma unroll
    for (int i = 0; i < 4; i++)
        #pragma unroll
        for (int j = 0; j < 4; j++) acc[i][j] = 0.f;

    for (int kc = 0; kc < FIN; kc += 20) {
        for (int i = threadIdx.x; i < 64 * 20; i += 256) {
            int r = i / 20, c = i % 20;
            int n = n0 + r;
            sF[r][c] = (n < NNODES) ? feat[(long long)n * FIN + kc + c] : 0.f;
        }
        for (int i = threadIdx.x; i < 20 * 64; i += 256) {
            int r = i >> 6, c = i & 63;
            sW[r][c] = W1[(kc + r) * HID + c];
        }
        __syncthreads();
        #pragma unroll
        for (int k = 0; k < 20; k++) {
            float a[4], b[4];
            #pragma unroll
            for (int j = 0; j < 4; j++) { a[j] = sF[ty * 4 + j][k]; b[j] = sW[k][tx * 4 + j]; }
            #pragma unroll
            for (int i = 0; i < 4; i++)
                #pragma unroll
                for (int j = 0; j < 4; j++) acc[i][j] = fmaf(a[i], b[j], acc[i][j]);
        }
        __syncthreads();
    }

    #pragma unroll
    for (int i = 0; i < 4; i++)
        #pragma unroll
        for (int j = 0; j < 4; j++)
            sH[ty * 4 + i][tx * 4 + j] = fmaxf(acc[i][j] + sB1[tx * 4 + j], 0.f);
    __syncthreads();

    float acc2[4][4];
    #pragma unroll
    for (int i = 0; i < 4; i++)
        #pragma unroll
        for (int j = 0; j < 4; j++) acc2[i][j] = 0.f;
    #pragma unroll 8
    for (int k = 0; k < 64; k++) {
        float a[4], b[4];
        #pragma unroll
        for (int j = 0; j < 4; j++) { a[j] = sH[ty * 4 + j][k]; b[j] = sW2[k][tx * 4 + j]; }
        #pragma unroll
        for (int i = 0; i < 4; i++)
            #pragma unroll
            for (int j = 0; j < 4; j++) acc2[i][j] = fmaf(a[i], b[j], acc2[i][j]);
    }
    #pragma unroll
    for (int i = 0; i < 4; i++) {
        int n = n0 + ty * 4 + i;
        if (n < NNODES) {
            #pragma unroll
            for (int j = 0; j < 4; j++)
                g_X[(long long)n * 64 + tx * 4 + j] = acc2[i][j] + sB2[tx * 4 + j];
        }
    }
}

// ---------------- fused SpMV hop: Tx_d = A*Tx_{d-1}; H += c_d*Tx_d ------
// 16 threads per dst node (2 nodes/warp), one float4 per lane: halves the
// gather LDG issue count vs 32xfloat2 at identical L2 traffic. Pure
// gather, no atomics: each half-warp exclusively owns its rows.
// Hop 1 seeds H = (1+c0)*X + c1*Tx_1 (no separate hinit pass).
// Cache policy: CSR meta + H are dead after this kernel -> streaming
// (__ldcs/__stcs). The dst (Tx_d) write is NOT streaming: it is the next
// hop's high-reuse gather operand and must stay L2-resident.
// On the last hop, fold log_softmax (16-lane xor-shuffle reduction) in.
__global__ __launch_bounds__(256) void k_spmv(int d, int srcsel, float* __restrict__ out) {
    int idx = blockIdx.x * blockDim.x + threadIdx.x;
    int n = idx >> 4;            // node per 16-thread group
    int lane = idx & 15;         // float4 column 0..15
    if (n >= NNODES) return;

    const float4* __restrict__ src =
        (const float4*)(srcsel == 0 ? g_X : (srcsel == 1 ? g_A : g_B));
    float4* dst = (float4*)((d & 1) ? g_B : g_A);

    int e  = __ldg(&g_rowptr[n]);
    int e1 = __ldg(&g_rowend[n]);
    float4 acc = make_float4(0.f, 0.f, 0.f, 0.f);

    // 8-deep software pipeline: covers ~250-cyc L2-hit latency
    for (; e + 8 <= e1; e += 8) {
        int2 m[8];
        #pragma unroll
        for (int j = 0; j < 8; j++) m[j] = __ldcs(&g_csr[e + j]);
        float4 v[8];
        #pragma unroll
        for (int j = 0; j < 8; j++) v[j] = src[m[j].x * 16 + lane];
        #pragma unroll
        for (int j = 0; j < 8; j++) {
            float w = __int_as_float(m[j].y);
            acc.x = fmaf(w, v[j].x, acc.x);
            acc.y = fmaf(w, v[j].y, acc.y);
            acc.z = fmaf(w, v[j].z, acc.z);
            acc.w = fmaf(w, v[j].w, acc.w);
        }
    }
    for (; e < e1; e++) {
        int2 m = __ldcs(&g_csr[e]);
        float w = __int_as_float(m.y);
        float4 v = src[m.x * 16 + lane];
        acc.x = fmaf(w, v.x, acc.x);
        acc.y = fmaf(w, v.y, acc.y);
        acc.z = fmaf(w, v.z, acc.z);
        acc.w = fmaf(w, v.w, acc.w);
    }

    float c = g_coeff[d];
    int base = n * 16 + lane;
    float4* H4 = (float4*)g_H;

    float4 h;
    if (d == 1) {
        // seed: H = (1+c0)*X + c1*Tx_1   (src == X on hop 1)
        float s0 = 1.0f + g_coeff[0];
        float4 x0 = ((const float4*)g_X)[base];
        h.x = fmaf(c, acc.x, s0 * x0.x);
        h.y = fmaf(c, acc.y, s0 * x0.y);
        h.z = fmaf(c, acc.z, s0 * x0.z);
        h.w = fmaf(c, acc.w, s0 * x0.w);
    } else {
        h = __ldcs(&H4[base]);
        h.x = fmaf(c, acc.x, h.x);
        h.y = fmaf(c, acc.y, h.y);
        h.z = fmaf(c, acc.z, h.z);
        h.w = fmaf(c, acc.w, h.w);
    }

    if (d < DH) {
        dst[base] = acc;          // keep resident: next hop's gather operand
        __stcs(&H4[base], h);     // dead until next hop's epilogue
    } else {
        // fused log_softmax over the 64-class row held by this 16-lane group
        float m = fmaxf(fmaxf(h.x, h.y), fmaxf(h.z, h.w));
        #pragma unroll
        for (int o = 8; o; o >>= 1) m = fmaxf(m, __shfl_xor_sync(0xFFFFFFFFu, m, o));
        float sm = expf(h.x - m) + expf(h.y - m) + expf(h.z - m) + expf(h.w - m);
        #pragma unroll
        for (int o = 8; o; o >>= 1) sm += __shfl_xor_sync(0xFFFFFFFFu, sm, o);
        float l = m + logf(sm);
        __stcs(&((float4*)out)[base],
               make_float4(h.x - l, h.y - l, h.z - l, h.w - l));
    }
}

// ---------------- launch ------------------------------------------------
// k_mlp is scheduled early (independent of graph preprocessing) so the
// harness's fixed ncu capture window (-s 5 -c 1) lands on it next profile.
extern "C" void kernel_launch(void* const* d_in, const int* in_sizes, int n_in,
                              void* d_out, int out_size) {
    const float* feat  = (const float*)d_in[0];
    const void*  edges = d_in[1];
    const float* W1    = (const float*)d_in[2];
    const float* b1    = (const float*)d_in[3];
    const float* W2    = (const float*)d_in[4];
    const float* b2    = (const float*)d_in[5];
    const float* alpha = (const float*)d_in[6];
    const float* beta  = (const float*)d_in[7];
    float* out = (float*)d_out;

    const int T = 256;
    k_init0<<<(NNODES + T - 1) / T, T>>>();
    k_detect<<<1, 256>>>((const int*)edges);
    k_deg<<<(NEDGES + T - 1) / T, T>>>(edges);
    k_mlp<<<(NNODES + 63) / 64, 256>>>(feat, W1, b1, W2, b2);   // profiled slot
    k_dinv<<<(NNODES + T - 1) / T, T>>>();
    k_scan1<<<NB, 256>>>();
    k_scan2<<<1, 512>>>();
    k_scan3<<<NB, 256>>>();
    k_fill<<<(NEDGES + T - 1) / T, T>>>(edges);
    k_coeff<<<1, 32>>>(alpha, beta);

    const int spmv_blocks = (NNODES * 16 + T - 1) / T;
    for (int d = 1; d <= DH; d++) {
        int srcsel = (d == 1) ? 0 : (((d - 1) & 1) ? 2 : 1);  // prev hop's dst
        k_spmv<<<spmv_blocks, T>>>(d, srcsel, out);
    }
}

// round 15
// speedup vs baseline: 1.1161x; 1.0165x over previous
#include <cuda_runtime.h>
#include <cstdint>

// Problem constants (fixed-shape problem)
#define NNODES 100000
#define NEDGES 3200000
#define FIN    500
#define HID    64
#define NC     64
#define KF     5
#define DH     10
#define NF     (NNODES * 64)
#define NB     ((NNODES + 255) / 256)   // 391 scan blocks

// ---------------- device scratch (no allocation allowed) ----------------
__device__ float g_X[NF];        // MLP output (Tx_0)
__device__ float g_A[NF];        // ping
__device__ float g_B[NF];        // pong
__device__ float g_H[NF];        // hidden accumulator (seeded in hop 1)
__device__ int2  g_csr[NEDGES];  // {src_node, weight_bits}, grouped by dst
__device__ int   g_rowptr[NNODES];
__device__ int   g_rowend[NNODES];  // fill cursor; after fill == row end
__device__ int   g_cnt[NNODES];     // in-degree histogram (by dst)
__device__ int   g_deg[NNODES];     // out-degree (by src, non-loop)
__device__ float g_dinv[NNODES];
__device__ int   g_bsum[NB + 1];
__device__ float g_coeff[16];
__device__ int   g_is64;

// ---------------- edge access (int32 or int64, runtime-detected) --------
__device__ __forceinline__ void load_edge(const void* edges, int e, int& s, int& d) {
    if (g_is64) {
        s = (int)((const long long*)edges)[e];
        d = (int)((const long long*)edges)[NEDGES + e];
    } else {
        s = ((const int*)edges)[e];
        d = ((const int*)edges)[NEDGES + e];
    }
}

// ---------------- init: zero counters, assume int64 until disproven -----
__global__ void k_init0() {
    int i = blockIdx.x * blockDim.x + threadIdx.x;
    if (i < NNODES) { g_deg[i] = 0; g_cnt[i] = 0; }
    if (i == 0) g_is64 = 1;
}

// If data is int64, high words of values < 2^31 are all zero; if int32,
// odd words are random node IDs (prob of 4096 zeros ~ 0). Samples stay
// within the first row so int32 buffers are never read out of bounds.
__global__ void k_detect(const int* e32) {
    bool nz = false;
    for (int j = threadIdx.x; j < 4096; j += blockDim.x)
        if (e32[2 * j + 1] != 0) nz = true;
    if (nz) g_is64 = 0;   // benign race: all writers store 0
}

// ---------------- degree (by src) and in-degree histogram (by dst) ------
__global__ void k_deg(const void* edges) {
    int e = blockIdx.x * blockDim.x + threadIdx.x;
    if (e >= NEDGES) return;
    int s, d; load_edge(edges, e, s, d);
    if (s != d) {
        atomicAdd(&g_deg[s], 1);
        atomicAdd(&g_cnt[d], 1);
    }
}

__global__ void k_dinv() {
    int i = blockIdx.x * blockDim.x + threadIdx.x;
    if (i >= NNODES) return;
    int d = g_deg[i];
    g_dinv[i] = (d > 0) ? rsqrtf((float)d) : 0.0f;
}

// ---------------- exclusive scan of g_cnt -> g_rowptr (3 kernels) -------
__global__ void k_scan1() {   // per-block Hillis-Steele, 256/block
    __shared__ int sh[256];
    int i = blockIdx.x * 256 + threadIdx.x;
    int v = (i < NNODES) ? g_cnt[i] : 0;
    sh[threadIdx.x] = v;
    __syncthreads();
    int acc = v;
    #pragma unroll
    for (int o = 1; o < 256; o <<= 1) {
        int t = (threadIdx.x >= o) ? sh[threadIdx.x - o] : 0;
        __syncthreads();
        acc += t;
        sh[threadIdx.x] = acc;
        __syncthreads();
    }
    if (i < NNODES) g_rowptr[i] = acc - v;   // exclusive within block
    if (threadIdx.x == 255) g_bsum[blockIdx.x] = acc;
}

__global__ void k_scan2() {   // single block scans NB block sums (exclusive)
    __shared__ int sh[512];
    int v = (threadIdx.x < NB) ? g_bsum[threadIdx.x] : 0;
    sh[threadIdx.x] = v;
    __syncthreads();
    int acc = v;
    #pragma unroll
    for (int o = 1; o < 512; o <<= 1) {
        int t = (threadIdx.x >= o) ? sh[threadIdx.x - o] : 0;
        __syncthreads();
        acc += t;
        sh[threadIdx.x] = acc;
        __syncthreads();
    }
    if (threadIdx.x < NB) g_bsum[threadIdx.x] = acc - v;  // exclusive
}

__global__ void k_scan3() {   // add block offsets; init fill cursor
    int i = blockIdx.x * 256 + threadIdx.x;
    if (i >= NNODES) return;
    int r = g_rowptr[i] + g_bsum[blockIdx.x];
    g_rowptr[i] = r;
    g_rowend[i] = r;          // cursor starts at row base
}

// ---------------- CSR fill: weight folded in ----------------------------
__global__ void k_fill(const void* edges) {
    int e = blockIdx.x * blockDim.x + threadIdx.x;
    if (e >= NEDGES) return;
    int s, d; load_edge(edges, e, s, d);
    if (s == d) return;
    // lam = 2*max(max(w_off),1) = 2 since all w_off <= 0 -> scale=1, diag=0
    float w = -(g_dinv[s] * g_dinv[d]);
    int pos = atomicAdd(&g_rowend[d], 1);
    g_csr[pos] = make_int2(s, __float_as_int(w));
}

// ---------------- Taylor coefficients: coeff = alpha@SINC + beta@COSC ---
__global__ void k_coeff(const float* __restrict__ alpha, const float* __restrict__ beta) {
    int d = threadIdx.x;
    if (d > DH) return;
    double acc = 0.0;
    for (int k = 0; k < KF; k++) {
        double x = (double)(k + 1) * 3.14159265358979323846;  // OMEGA = 1
        double fact = 1.0, xp = 1.0;
        for (int j = 1; j <= d; j++) { fact *= (double)j; xp *= x; }
        float sc = 0.f, cc = 0.f;
        if ((d & 1) == 0) { int m = d / 2;       cc = (float)(((m & 1) ? -1.0 : 1.0) * xp / fact); }
        else              { int m = (d - 1) / 2; sc = (float)(((m & 1) ? -1.0 : 1.0) * xp / fact); }
        acc += (double)alpha[k] * (double)sc + (double)beta[k] * (double)cc;
    }
    g_coeff[d] = (float)acc;
}

// ---------------- fused 2-layer MLP: X = relu(F@W1+b1)@W2+b2 ------------
// Block: 64 nodes x 64 outputs. 256 threads as 16x16, 4x4 per thread.
// Both GEMMs read operands as aligned LDS.128: the A tiles are stored
// TRANSPOSED ([k][node], pad 68) so a-operand is one float4 broadcast;
// b-operand rows are contiguous. Inner loop: 2 LDS.128 + 16 FFMA per k
// (was 8 scalar LDS + 16 FFMA + addressing ALU).
__global__ __launch_bounds__(256) void k_mlp(
    const float* __restrict__ feat, const float* __restrict__ W1,
    const float* __restrict__ b1,  const float* __restrict__ W2,
    const float* __restrict__ b2)
{
    __shared__ float sFT[20][68];   // transposed feature tile [k][node]
    __shared__ float sW[20][64];    // W1 tile [k][out]
    __shared__ float sHT[64][68];   // transposed hidden [k][node]
    __shared__ float sW2[64][64];   // W2 [k][out]
    __shared__ float sB1[64];
    __shared__ float sB2[64];

    const int tx = threadIdx.x & 15;
    const int ty = threadIdx.x >> 4;
    const int n0 = blockIdx.x * 64;

    for (int i = threadIdx.x; i < 64 * 64; i += 256) sW2[i >> 6][i & 63] = W2[i];
    if (threadIdx.x < 64) { sB1[threadIdx.x] = b1[threadIdx.x]; sB2[threadIdx.x] = b2[threadIdx.x]; }

    float acc[4][4];
    #pragma unroll
    for (int i = 0; i < 4; i++)
        #pragma unroll
        for (int j = 0; j < 4; j++) acc[i][j] = 0.f;

    for (int kc = 0; kc < FIN; kc += 20) {
        for (int i = threadIdx.x; i < 64 * 20; i += 256) {
            int r = i / 20, c = i % 20;
            int n = n0 + r;
            sFT[c][r] = (n < NNODES) ? feat[(long long)n * FIN + kc + c] : 0.f;
        }
        for (int i = threadIdx.x; i < 20 * 64; i += 256) {
            int r = i >> 6, c = i & 63;
            sW[r][c] = W1[(kc + r) * HID + c];
        }
        __syncthreads();
        #pragma unroll
        for (int k = 0; k < 20; k++) {
            float4 a4 = *(const float4*)&sFT[k][ty * 4];
            float4 b4 = *(const float4*)&sW[k][tx * 4];
            float a[4] = {a4.x, a4.y, a4.z, a4.w};
            float b[4] = {b4.x, b4.y, b4.z, b4.w};
            #pragma unroll
            for (int i = 0; i < 4; i++)
                #pragma unroll
                for (int j = 0; j < 4; j++) acc[i][j] = fmaf(a[i], b[j], acc[i][j]);
        }
        __syncthreads();
    }

    // bias + relu -> transposed hidden tile
    #pragma unroll
    for (int i = 0; i < 4; i++)
        #pragma unroll
        for (int j = 0; j < 4; j++)
            sHT[tx * 4 + j][ty * 4 + i] = fmaxf(acc[i][j] + sB1[tx * 4 + j], 0.f);
    __syncthreads();

    float acc2[4][4];
    #pragma unroll
    for (int i = 0; i < 4; i++)
        #pragma unroll
        for (int j = 0; j < 4; j++) acc2[i][j] = 0.f;
    #pragma unroll 16
    for (int k = 0; k < 64; k++) {
        float4 a4 = *(const float4*)&sHT[k][ty * 4];
        float4 b4 = *(const float4*)&sW2[k][tx * 4];
        float a[4] = {a4.x, a4.y, a4.z, a4.w};
        float b[4] = {b4.x, b4.y, b4.z, b4.w};
        #pragma unroll
        for (int i = 0; i < 4; i++)
            #pragma unroll
            for (int j = 0; j < 4; j++) acc2[i][j] = fmaf(a[i], b[j], acc2[i][j]);
    }
    #pragma unroll
    for (int i = 0; i < 4; i++) {
        int n = n0 + ty * 4 + i;
        if (n < NNODES) {
            #pragma unroll
            for (int j = 0; j < 4; j++)
                g_X[(long long)n * 64 + tx * 4 + j] = acc2[i][j] + sB2[tx * 4 + j];
        }
    }
}

// ---------------- fused SpMV hop: Tx_d = A*Tx_{d-1}; H += c_d*Tx_d ------
// 16 threads per dst node (2 nodes/warp), one float4 per lane: halves the
// gather LDG issue count vs 32xfloat2 at identical L2 traffic. Pure
// gather, no atomics: each half-warp exclusively owns its rows.
// Hop 1 seeds H = (1+c0)*X + c1*Tx_1 (no separate hinit pass).
// Cache policy: CSR meta + H are dead after this kernel -> streaming
// (__ldcs/__stcs). The dst (Tx_d) write is NOT streaming: it is the next
// hop's high-reuse gather operand and must stay L2-resident.
// On the last hop, fold log_softmax (16-lane xor-shuffle reduction) in.
__global__ __launch_bounds__(256) void k_spmv(int d, int srcsel, float* __restrict__ out) {
    int idx = blockIdx.x * blockDim.x + threadIdx.x;
    int n = idx >> 4;            // node per 16-thread group
    int lane = idx & 15;         // float4 column 0..15
    if (n >= NNODES) return;

    const float4* __restrict__ src =
        (const float4*)(srcsel == 0 ? g_X : (srcsel == 1 ? g_A : g_B));
    float4* dst = (float4*)((d & 1) ? g_B : g_A);

    int e  = __ldg(&g_rowptr[n]);
    int e1 = __ldg(&g_rowend[n]);
    float4 acc = make_float4(0.f, 0.f, 0.f, 0.f);

    // 8-deep software pipeline: covers ~250-cyc L2-hit latency
    for (; e + 8 <= e1; e += 8) {
        int2 m[8];
        #pragma unroll
        for (int j = 0; j < 8; j++) m[j] = __ldcs(&g_csr[e + j]);
        float4 v[8];
        #pragma unroll
        for (int j = 0; j < 8; j++) v[j] = src[m[j].x * 16 + lane];
        #pragma unroll
        for (int j = 0; j < 8; j++) {
            float w = __int_as_float(m[j].y);
            acc.x = fmaf(w, v[j].x, acc.x);
            acc.y = fmaf(w, v[j].y, acc.y);
            acc.z = fmaf(w, v[j].z, acc.z);
            acc.w = fmaf(w, v[j].w, acc.w);
        }
    }
    for (; e < e1; e++) {
        int2 m = __ldcs(&g_csr[e]);
        float w = __int_as_float(m.y);
        float4 v = src[m.x * 16 + lane];
        acc.x = fmaf(w, v.x, acc.x);
        acc.y = fmaf(w, v.y, acc.y);
        acc.z = fmaf(w, v.z, acc.z);
        acc.w = fmaf(w, v.w, acc.w);
    }

    float c = g_coeff[d];
    int base = n * 16 + lane;
    float4* H4 = (float4*)g_H;

    float4 h;
    if (d == 1) {
        // seed: H = (1+c0)*X + c1*Tx_1   (src == X on hop 1)
        float s0 = 1.0f + g_coeff[0];
        float4 x0 = ((const float4*)g_X)[base];
        h.x = fmaf(c, acc.x, s0 * x0.x);
        h.y = fmaf(c, acc.y, s0 * x0.y);
        h.z = fmaf(c, acc.z, s0 * x0.z);
        h.w = fmaf(c, acc.w, s0 * x0.w);
    } else {
        h = __ldcs(&H4[base]);
        h.x = fmaf(c, acc.x, h.x);
        h.y = fmaf(c, acc.y, h.y);
        h.z = fmaf(c, acc.z, h.z);
        h.w = fmaf(c, acc.w, h.w);
    }

    if (d < DH) {
        dst[base] = acc;          // keep resident: next hop's gather operand
        __stcs(&H4[base], h);     // dead until next hop's epilogue
    } else {
        // fused log_softmax over the 64-class row held by this 16-lane group
        float m = fmaxf(fmaxf(h.x, h.y), fmaxf(h.z, h.w));
        #pragma unroll
        for (int o = 8; o; o >>= 1) m = fmaxf(m, __shfl_xor_sync(0xFFFFFFFFu, m, o));
        float sm = expf(h.x - m) + expf(h.y - m) + expf(h.z - m) + expf(h.w - m);
        #pragma unroll
        for (int o = 8; o; o >>= 1) sm += __shfl_xor_sync(0xFFFFFFFFu, sm, o);
        float l = m + logf(sm);
        __stcs(&((float4*)out)[base],
               make_float4(h.x - l, h.y - l, h.z - l, h.w - l));
    }
}

// ---------------- launch ------------------------------------------------
// k_mlp stays in the ncu capture window (-s 5 -c 1) to verify the fma%
// prediction for the vectorized inner loop.
extern "C" void kernel_launch(void* const* d_in, const int* in_sizes, int n_in,
                              void* d_out, int out_size) {
    const float* feat  = (const float*)d_in[0];
    const void*  edges = d_in[1];
    const float* W1    = (const float*)d_in[2];
    const float* b1    = (const float*)d_in[3];
    const float* W2    = (const float*)d_in[4];
    const float* b2    = (const float*)d_in[5];
    const float* alpha = (const float*)d_in[6];
    const float* beta  = (const float*)d_in[7];
    float* out = (float*)d_out;

    const int T = 256;
    k_init0<<<(NNODES + T - 1) / T, T>>>();
    k_detect<<<1, 256>>>((const int*)edges);
    k_deg<<<(NEDGES + T - 1) / T, T>>>(edges);
    k_mlp<<<(NNODES + 63) / 64, 256>>>(feat, W1, b1, W2, b2);   // profiled slot
    k_dinv<<<(NNODES + T - 1) / T, T>>>();
    k_scan1<<<NB, 256>>>();
    k_scan2<<<1, 512>>>();
    k_scan3<<<NB, 256>>>();
    k_fill<<<(NEDGES + T - 1) / T, T>>>(edges);
    k_coeff<<<1, 32>>>(alpha, beta);

    const int spmv_blocks = (NNODES * 16 + T - 1) / T;
    for (int d = 1; d <= DH; d++) {
        int srcsel = (d == 1) ? 0 : (((d - 1) & 1) ? 2 : 1);  // prev hop's dst
        k_spmv<<<spmv_blocks, T>>>(d, srcsel, out);
    }
}

// round 17
// speedup vs baseline: 1.3275x; 1.1894x over previous
#include <cuda_runtime.h>
#include <cstdint>

// Problem constants (fixed-shape problem)
#define NNODES 100000
#define NEDGES 3200000
#define FIN    500
#define HID    64
#define NC     64
#define KF     5
#define DH     10
#define NF     (NNODES * 64)
#define NB     ((NNODES + 255) / 256)   // 391 scan blocks

// ---------------- device scratch (no allocation allowed) ----------------
__device__ float g_X[NF];        // MLP output (Tx_0)
__device__ float g_A[NF];        // ping
__device__ float g_B[NF];        // pong
__device__ float g_H[NF];        // hidden accumulator (seeded in hop 1)
__device__ int2  g_csr[NEDGES];  // {src_node, weight_bits}, grouped by dst
__device__ int   g_rowptr[NNODES];
__device__ int   g_rowend[NNODES];  // fill cursor; after fill == row end
__device__ int   g_cnt[NNODES];     // in-degree histogram (by dst)
__device__ int   g_deg[NNODES];     // out-degree (by src, non-loop)
__device__ float g_dinv[NNODES];
__device__ int   g_bsum[NB + 1];
__device__ float g_coeff[16];
__device__ int   g_is64;

// ---------------- edge access (int32 or int64, runtime-detected) --------
__device__ __forceinline__ void load_edge(const void* edges, int e, int& s, int& d) {
    if (g_is64) {
        s = (int)((const long long*)edges)[e];
        d = (int)((const long long*)edges)[NEDGES + e];
    } else {
        s = ((const int*)edges)[e];
        d = ((const int*)edges)[NEDGES + e];
    }
}

// ---------------- init: zero counters, assume int64 until disproven -----
__global__ void k_init0() {
    int i = blockIdx.x * blockDim.x + threadIdx.x;
    if (i < NNODES) { g_deg[i] = 0; g_cnt[i] = 0; }
    if (i == 0) g_is64 = 1;
}

// If data is int64, high words of values < 2^31 are all zero; if int32,
// odd words are random node IDs (prob of 4096 zeros ~ 0). Samples stay
// within the first row so int32 buffers are never read out of bounds.
__global__ void k_detect(const int* e32) {
    bool nz = false;
    for (int j = threadIdx.x; j < 4096; j += blockDim.x)
        if (e32[2 * j + 1] != 0) nz = true;
    if (nz) g_is64 = 0;   // benign race: all writers store 0
}

// ---------------- degree (by src) and in-degree histogram (by dst) ------
__global__ void k_deg(const void* edges) {
    int e = blockIdx.x * blockDim.x + threadIdx.x;
    if (e >= NEDGES) return;
    int s, d; load_edge(edges, e, s, d);
    if (s != d) {
        atomicAdd(&g_deg[s], 1);
        atomicAdd(&g_cnt[d], 1);
    }
}

__global__ void k_dinv() {
    int i = blockIdx.x * blockDim.x + threadIdx.x;
    if (i >= NNODES) return;
    int d = g_deg[i];
    g_dinv[i] = (d > 0) ? rsqrtf((float)d) : 0.0f;
}

// ---------------- exclusive scan of g_cnt -> g_rowptr (3 kernels) -------
__global__ void k_scan1() {   // per-block Hillis-Steele, 256/block
    __shared__ int sh[256];
    int i = blockIdx.x * 256 + threadIdx.x;
    int v = (i < NNODES) ? g_cnt[i] : 0;
    sh[threadIdx.x] = v;
    __syncthreads();
    int acc = v;
    #pragma unroll
    for (int o = 1; o < 256; o <<= 1) {
        int t = (threadIdx.x >= o) ? sh[threadIdx.x - o] : 0;
        __syncthreads();
        acc += t;
        sh[threadIdx.x] = acc;
        __syncthreads();
    }
    if (i < NNODES) g_rowptr[i] = acc - v;   // exclusive within block
    if (threadIdx.x == 255) g_bsum[blockIdx.x] = acc;
}

__global__ void k_scan2() {   // single block scans NB block sums (exclusive)
    __shared__ int sh[512];
    int v = (threadIdx.x < NB) ? g_bsum[threadIdx.x] : 0;
    sh[threadIdx.x] = v;
    __syncthreads();
    int acc = v;
    #pragma unroll
    for (int o = 1; o < 512; o <<= 1) {
        int t = (threadIdx.x >= o) ? sh[threadIdx.x - o] : 0;
        __syncthreads();
        acc += t;
        sh[threadIdx.x] = acc;
        __syncthreads();
    }
    if (threadIdx.x < NB) g_bsum[threadIdx.x] = acc - v;  // exclusive
}

__global__ void k_scan3() {   // add block offsets; init fill cursor
    int i = blockIdx.x * 256 + threadIdx.x;
    if (i >= NNODES) return;
    int r = g_rowptr[i] + g_bsum[blockIdx.x];
    g_rowptr[i] = r;
    g_rowend[i] = r;          // cursor starts at row base
}

// ---------------- CSR fill: weight folded in ----------------------------
__global__ void k_fill(const void* edges) {
    int e = blockIdx.x * blockDim.x + threadIdx.x;
    if (e >= NEDGES) return;
    int s, d; load_edge(edges, e, s, d);
    if (s == d) return;
    // lam = 2*max(max(w_off),1) = 2 since all w_off <= 0 -> scale=1, diag=0
    float w = -(g_dinv[s] * g_dinv[d]);
    int pos = atomicAdd(&g_rowend[d], 1);
    g_csr[pos] = make_int2(s, __float_as_int(w));
}

// ---------------- Taylor coefficients: coeff = alpha@SINC + beta@COSC ---
__global__ void k_coeff(const float* __restrict__ alpha, const float* __restrict__ beta) {
    int d = threadIdx.x;
    if (d > DH) return;
    double acc = 0.0;
    for (int k = 0; k < KF; k++) {
        double x = (double)(k + 1) * 3.14159265358979323846;  // OMEGA = 1
        double fact = 1.0, xp = 1.0;
        for (int j = 1; j <= d; j++) { fact *= (double)j; xp *= x; }
        float sc = 0.f, cc = 0.f;
        if ((d & 1) == 0) { int m = d / 2;       cc = (float)(((m & 1) ? -1.0 : 1.0) * xp / fact); }
        else              { int m = (d - 1) / 2; sc = (float)(((m & 1) ? -1.0 : 1.0) * xp / fact); }
        acc += (double)alpha[k] * (double)sc + (double)beta[k] * (double)cc;
    }
    g_coeff[d] = (float)acc;
}

// ---------------- fused 2-layer MLP: X = relu(F@W1+b1)@W2+b2 ------------
// Block: 64 nodes x 64 outputs. 256 threads as 16x16, 4x4 per thread.
// GEMM1 is DOUBLE-BUFFERED with register prefetch: the per-chunk feat/W1
// global loads issue during the previous chunk's compute, so their DRAM
// latency (previously exposed at every __syncthreads, the measured
// issue=48.7% stall) hides behind FFMA work. One sync per chunk (safe:
// a warp can only reach the store into buf[c&1] at iter c+2 after all
// warps passed sync(c+1), which follows their compute(c)).
// sW2 shares smem with the dead-by-then double buffers (static 48KB cap).
__global__ __launch_bounds__(256) void k_mlp(
    const float* __restrict__ feat, const float* __restrict__ W1,
    const float* __restrict__ b1,  const float* __restrict__ W2,
    const float* __restrict__ b2)
{
    struct SmemA { float ft[2][20][68]; float w[2][20][64]; };  // 21.1 KB
    struct SmemB { float w2[64][64]; };                         // 16.4 KB
    __shared__ union { SmemA a; SmemB b; } sm;
    __shared__ float sHT[64][68];   // transposed hidden [k][node]
    __shared__ float sB1[64];
    __shared__ float sB2[64];

    const int tid = threadIdx.x;
    const int tx = tid & 15;
    const int ty = tid >> 4;
    const int n0 = blockIdx.x * 64;

    if (tid < 64) { sB1[tid] = b1[tid]; sB2[tid] = b2[tid]; }

    // Precompute fill indices (fixed across chunks; only kc advances)
    int fr[5], fc[5];
    const float* fptr[5];
    bool fvalid[5];
    #pragma unroll
    for (int j = 0; j < 5; j++) {
        int i = tid + j * 256;
        fr[j] = i / 20; fc[j] = i % 20;
        int n = n0 + fr[j];
        fvalid[j] = (n < NNODES);
        fptr[j] = feat + (long long)(fvalid[j] ? n : 0) * FIN + fc[j];
    }

    // Prefetch chunk 0 into registers
    float pf[5], pw[5];
    #pragma unroll
    for (int j = 0; j < 5; j++) pf[j] = fvalid[j] ? fptr[j][0] : 0.f;
    #pragma unroll
    for (int j = 0; j < 5; j++) pw[j] = W1[tid + j * 256];

    float acc[4][4];
    #pragma unroll
    for (int i = 0; i < 4; i++)
        #pragma unroll
        for (int j = 0; j < 4; j++) acc[i][j] = 0.f;

    for (int c = 0; c < 25; c++) {
        const int buf = c & 1;
        // store prefetched regs -> smem tile (transposed A)
        #pragma unroll
        for (int j = 0; j < 5; j++) sm.a.ft[buf][fc[j]][fr[j]] = pf[j];
        #pragma unroll
        for (int j = 0; j < 5; j++) {
            int i = tid + j * 256;
            sm.a.w[buf][i >> 6][i & 63] = pw[j];
        }
        __syncthreads();
        // prefetch next chunk (latency overlaps compute below)
        if (c < 24) {
            #pragma unroll
            for (int j = 0; j < 5; j++) pf[j] = fvalid[j] ? fptr[j][(c + 1) * 20] : 0.f;
            #pragma unroll
            for (int j = 0; j < 5; j++) pw[j] = W1[(c + 1) * 20 * 64 + tid + j * 256];
        }
        #pragma unroll
        for (int k = 0; k < 20; k++) {
            float4 a4 = *(const float4*)&sm.a.ft[buf][k][ty * 4];
            float4 b4 = *(const float4*)&sm.a.w[buf][k][tx * 4];
            float a[4] = {a4.x, a4.y, a4.z, a4.w};
            float b[4] = {b4.x, b4.y, b4.z, b4.w};
            #pragma unroll
            for (int i = 0; i < 4; i++)
                #pragma unroll
                for (int j = 0; j < 4; j++) acc[i][j] = fmaf(a[i], b[j], acc[i][j]);
        }
    }

    // bias + relu -> transposed hidden tile
    #pragma unroll
    for (int i = 0; i < 4; i++)
        #pragma unroll
        for (int j = 0; j < 4; j++)
            sHT[tx * 4 + j][ty * 4 + i] = fmaxf(acc[i][j] + sB1[tx * 4 + j], 0.f);
    __syncthreads();   // sHT visible; all reads of sm.a done

    // fill sW2 into the union region (W2 is L2-hot after first wave)
    for (int i = tid; i < 64 * 64; i += 256) sm.b.w2[i >> 6][i & 63] = W2[i];
    __syncthreads();

    float acc2[4][4];
    #pragma unroll
    for (int i = 0; i < 4; i++)
        #pragma unroll
        for (int j = 0; j < 4; j++) acc2[i][j] = 0.f;
    #pragma unroll 16
    for (int k = 0; k < 64; k++) {
        float4 a4 = *(const float4*)&sHT[k][ty * 4];
        float4 b4 = *(const float4*)&sm.b.w2[k][tx * 4];
        float a[4] = {a4.x, a4.y, a4.z, a4.w};
        float b[4] = {b4.x, b4.y, b4.z, b4.w};
        #pragma unroll
        for (int i = 0; i < 4; i++)
            #pragma unroll
            for (int j = 0; j < 4; j++) acc2[i][j] = fmaf(a[i], b[j], acc2[i][j]);
    }
    #pragma unroll
    for (int i = 0; i < 4; i++) {
        int n = n0 + ty * 4 + i;
        if (n < NNODES) {
            #pragma unroll
            for (int j = 0; j < 4; j++)
                g_X[(long long)n * 64 + tx * 4 + j] = acc2[i][j] + sB2[tx * 4 + j];
        }
    }
}

// ---------------- fused SpMV hop: Tx_d = A*Tx_{d-1}; H += c_d*Tx_d ------
// 16 threads per dst node (2 nodes/warp), one float4 per lane: halves the
// gather LDG issue count vs 32xfloat2 at identical L2 traffic. Pure
// gather, no atomics: each half-warp exclusively owns its rows.
// Hop 1 seeds H = (1+c0)*X + c1*Tx_1 (no separate hinit pass).
// Cache policy: CSR meta + H are dead after this kernel -> streaming
// (__ldcs/__stcs). The dst (Tx_d) write is NOT streaming: it is the next
// hop's high-reuse gather operand and must stay L2-resident.
// On the last hop, fold log_softmax (16-lane xor-shuffle reduction) in.
__global__ __launch_bounds__(256) void k_spmv(int d, int srcsel, float* __restrict__ out) {
    int idx = blockIdx.x * blockDim.x + threadIdx.x;
    int n = idx >> 4;            // node per 16-thread group
    int lane = idx & 15;         // float4 column 0..15
    if (n >= NNODES) return;

    const float4* __restrict__ src =
        (const float4*)(srcsel == 0 ? g_X : (srcsel == 1 ? g_A : g_B));
    float4* dst = (float4*)((d & 1) ? g_B : g_A);

    int e  = __ldg(&g_rowptr[n]);
    int e1 = __ldg(&g_rowend[n]);
    float4 acc = make_float4(0.f, 0.f, 0.f, 0.f);

    // 8-deep software pipeline: covers ~250-cyc L2-hit latency
    for (; e + 8 <= e1; e += 8) {
        int2 m[8];
        #pragma unroll
        for (int j = 0; j < 8; j++) m[j] = __ldcs(&g_csr[e + j]);
        float4 v[8];
        #pragma unroll
        for (int j = 0; j < 8; j++) v[j] = src[m[j].x * 16 + lane];
        #pragma unroll
        for (int j = 0; j < 8; j++) {
            float w = __int_as_float(m[j].y);
            acc.x = fmaf(w, v[j].x, acc.x);
            acc.y = fmaf(w, v[j].y, acc.y);
            acc.z = fmaf(w, v[j].z, acc.z);
            acc.w = fmaf(w, v[j].w, acc.w);
        }
    }
    for (; e < e1; e++) {
        int2 m = __ldcs(&g_csr[e]);
        float w = __int_as_float(m.y);
        float4 v = src[m.x * 16 + lane];
        acc.x = fmaf(w, v.x, acc.x);
        acc.y = fmaf(w, v.y, acc.y);
        acc.z = fmaf(w, v.z, acc.z);
        acc.w = fmaf(w, v.w, acc.w);
    }

    float c = g_coeff[d];
    int base = n * 16 + lane;
    float4* H4 = (float4*)g_H;

    float4 h;
    if (d == 1) {
        // seed: H = (1+c0)*X + c1*Tx_1   (src == X on hop 1)
        float s0 = 1.0f + g_coeff[0];
        float4 x0 = ((const float4*)g_X)[base];
        h.x = fmaf(c, acc.x, s0 * x0.x);
        h.y = fmaf(c, acc.y, s0 * x0.y);
        h.z = fmaf(c, acc.z, s0 * x0.z);
        h.w = fmaf(c, acc.w, s0 * x0.w);
    } else {
        h = __ldcs(&H4[base]);
        h.x = fmaf(c, acc.x, h.x);
        h.y = fmaf(c, acc.y, h.y);
        h.z = fmaf(c, acc.z, h.z);
        h.w = fmaf(c, acc.w, h.w);
    }

    if (d < DH) {
        dst[base] = acc;          // keep resident: next hop's gather operand
        __stcs(&H4[base], h);     // dead until next hop's epilogue
    } else {
        // fused log_softmax over the 64-class row held by this 16-lane group
        float m = fmaxf(fmaxf(h.x, h.y), fmaxf(h.z, h.w));
        #pragma unroll
        for (int o = 8; o; o >>= 1) m = fmaxf(m, __shfl_xor_sync(0xFFFFFFFFu, m, o));
        float sm = expf(h.x - m) + expf(h.y - m) + expf(h.z - m) + expf(h.w - m);
        #pragma unroll
        for (int o = 8; o; o >>= 1) sm += __shfl_xor_sync(0xFFFFFFFFu, sm, o);
        float l = m + logf(sm);
        __stcs(&((float4*)out)[base],
               make_float4(h.x - l, h.y - l, h.z - l, h.w - l));
    }
}

// ---------------- launch ------------------------------------------------
// k_mlp stays in the ncu capture window (-s 5 -c 1) to verify the
// issue%/fma% prediction for the double-buffered mainloop.
extern "C" void kernel_launch(void* const* d_in, const int* in_sizes, int n_in,
                              void* d_out, int out_size) {
    const float* feat  = (const float*)d_in[0];
    const void*  edges = d_in[1];
    const float* W1    = (const float*)d_in[2];
    const float* b1    = (const float*)d_in[3];
    const float* W2    = (const float*)d_in[4];
    const float* b2    = (const float*)d_in[5];
    const float* alpha = (const float*)d_in[6];
    const float* beta  = (const float*)d_in[7];
    float* out = (float*)d_out;

    const int T = 256;
    k_init0<<<(NNODES + T - 1) / T, T>>>();
    k_detect<<<1, 256>>>((const int*)edges);
    k_deg<<<(NEDGES + T - 1) / T, T>>>(edges);
    k_mlp<<<(NNODES + 63) / 64, 256>>>(feat, W1, b1, W2, b2);   // profiled slot
    k_dinv<<<(NNODES + T - 1) / T, T>>>();
    k_scan1<<<NB, 256>>>();
    k_scan2<<<1, 512>>>();
    k_scan3<<<NB, 256>>>();
    k_fill<<<(NEDGES + T - 1) / T, T>>>(edges);
    k_coeff<<<1, 32>>>(alpha, beta);

    const int spmv_blocks = (NNODES * 16 + T - 1) / T;
    for (int d = 1; d <= DH; d++) {
        int srcsel = (d == 1) ? 0 : (((d - 1) & 1) ? 2 : 1);  // prev hop's dst
        k_spmv<<<spmv_blocks, T>>>(d, srcsel, out);
    }
}